// round 1
// baseline (speedup 1.0000x reference)
#include <cuda_runtime.h>
#include <cstdint>

// ---------------------------------------------------------------------------
// RipsECC: Euler characteristic curve of the Rips 1-skeleton.
//   B=4096 points, D=3, 64 bins, scale = 63/2 = 31.5, t_min = 0.
//   max pairwise distance = sqrt(3) < t_max=2  -> every i<j pair is an edge.
//   bin(d) = ceil(d * 31.5)  (in [0,55]); vertices: +4096 at bin 0.
//   out = cumsum over bins of (+4096 at bin0) - edge_histogram.
// ---------------------------------------------------------------------------

#define NPTS      4096
#define NSTEPS    64
#define NTHREADS  512
#define NWARPS    16                       // warps per block
#define NBLOCKS   (NPTS / 2 / NWARPS)      // 128: warp u handles rows {u, 4095-u}
#define PAD       4128                     // 4096 + 32 tail padding
#define HIST_WORDS (NWARPS * NSTEPS * 32)  // 32768 words = 128 KB
#define SMEM_FLOATS (3 * PAD + HIST_WORDS)
#define SMEM_BYTES  (SMEM_FLOATS * 4)      // 180608 B

__device__ int g_hist[NSTEPS];

__global__ void ecc_zero_kernel() {
    if (threadIdx.x < NSTEPS) g_hist[threadIdx.x] = 0;
}

// One pair: exact fp32 (no FMA contraction) to bit-match the reference:
//   d2 = ((dx*dx + dy*dy) + dz*dz); d = sqrt_rn(d2); t = ceil(d*31.5)
__device__ __forceinline__ void pair_body(float xi, float yi, float zi,
                                          const float* __restrict__ xs,
                                          const float* __restrict__ ys,
                                          const float* __restrict__ zs,
                                          unsigned* myhist, int j) {
    float dx = __fadd_rn(xi, -xs[j]);
    float dy = __fadd_rn(yi, -ys[j]);
    float dz = __fadd_rn(zi, -zs[j]);
    float d2 = __fadd_rn(__fadd_rn(__fmul_rn(dx, dx), __fmul_rn(dy, dy)),
                         __fmul_rn(dz, dz));
    float d  = __fsqrt_rn(d2);
    int   t  = __float2int_ru(__fmul_rn(d, 31.5f));
    t = min(t, NSTEPS - 1);
    // lane-owned slot: word index = t*32 + lane (bank == lane, conflict-free)
    myhist[t << 5] += 1u;
}

__device__ __forceinline__ void process_row(int i, int lane,
                                            const float* __restrict__ xs,
                                            const float* __restrict__ ys,
                                            const float* __restrict__ zs,
                                            unsigned* myhist) {
    if (i >= NPTS - 1) return;
    float xi = xs[i], yi = ys[i], zi = zs[i];
    int cnt   = NPTS - 1 - i;      // number of j's (j = i+1 .. 4095)
    int kfull = cnt >> 5;          // full-warp iterations
    int j = i + 1 + lane;
    int k = 0;
    for (; k + 4 <= kfull; k += 4) {
        pair_body(xi, yi, zi, xs, ys, zs, myhist, j);
        pair_body(xi, yi, zi, xs, ys, zs, myhist, j + 32);
        pair_body(xi, yi, zi, xs, ys, zs, myhist, j + 64);
        pair_body(xi, yi, zi, xs, ys, zs, myhist, j + 96);
        j += 128;
    }
    for (; k < kfull; k++) {
        pair_body(xi, yi, zi, xs, ys, zs, myhist, j);
        j += 32;
    }
    if (j < NPTS)   // tail (reads into zero-filled pad are safe; update guarded)
        pair_body(xi, yi, zi, xs, ys, zs, myhist, j);
}

extern __shared__ float smem_f[];

__global__ void __launch_bounds__(NTHREADS, 1)
rips_ecc_kernel(const float* __restrict__ x) {
    float* xs = smem_f;
    float* ys = smem_f + PAD;
    float* zs = smem_f + 2 * PAD;
    unsigned* hist = (unsigned*)(smem_f + 3 * PAD);  // [NWARPS][NSTEPS][32]

    const int tid = threadIdx.x;

    // Stage all 4096 points into shared (SoA), zero the 32-element pad.
    for (int idx = tid; idx < PAD; idx += NTHREADS) {
        float a = 0.f, b = 0.f, c = 0.f;
        if (idx < NPTS) {
            a = x[3 * idx + 0];
            b = x[3 * idx + 1];
            c = x[3 * idx + 2];
        }
        xs[idx] = a; ys[idx] = b; zs[idx] = c;
    }
    // Zero the per-warp histograms (128 KB) with 16B stores.
    uint4* h4 = (uint4*)hist;
    for (int idx = tid; idx < HIST_WORDS / 4; idx += NTHREADS)
        h4[idx] = make_uint4(0u, 0u, 0u, 0u);
    __syncthreads();

    const int warp = tid >> 5;
    const int lane = tid & 31;
    unsigned* myhist = hist + warp * (NSTEPS * 32) + lane;

    // Balanced triangular decomposition: warp-unit u owns rows u and 4095-u,
    // exactly 4095 pairs per warp.
    const int u = blockIdx.x * NWARPS + warp;
    process_row(u,            lane, xs, ys, zs, myhist);
    process_row(NPTS - 1 - u, lane, xs, ys, zs, myhist);

    __syncthreads();

    // Block reduction: warp w reduces bins [4w, 4w+4).
    #pragma unroll
    for (int bb = 0; bb < 4; bb++) {
        int b = warp * 4 + bb;
        unsigned s = 0;
        #pragma unroll
        for (int wi = 0; wi < NWARPS; wi++)
            s += hist[wi * (NSTEPS * 32) + (b << 5) + lane];
        #pragma unroll
        for (int o = 16; o > 0; o >>= 1)
            s += __shfl_down_sync(0xffffffffu, s, o);
        if (lane == 0)
            atomicAdd(&g_hist[b], (int)s);
    }
}

// ecc[t] = (t==0 ? 4096 : 0) - hist[t];  out = cumsum(ecc)  (exact in int)
__global__ void ecc_cumsum_kernel(float* __restrict__ out) {
    const int lane = threadIdx.x;  // 32 threads
    int e0 = (lane == 0 ? NPTS : 0) - g_hist[lane];
    int e1 = -g_hist[lane + 32];
    #pragma unroll
    for (int d = 1; d < 32; d <<= 1) {
        int t = __shfl_up_sync(0xffffffffu, e0, d);
        if (lane >= d) e0 += t;
    }
    int tot = __shfl_sync(0xffffffffu, e0, 31);
    #pragma unroll
    for (int d = 1; d < 32; d <<= 1) {
        int t = __shfl_up_sync(0xffffffffu, e1, d);
        if (lane >= d) e1 += t;
    }
    e1 += tot;
    out[lane]      = (float)e0;
    out[lane + 32] = (float)e1;
}

extern "C" void kernel_launch(void* const* d_in, const int* in_sizes, int n_in,
                              void* d_out, int out_size) {
    (void)in_sizes; (void)n_in; (void)out_size;
    const float* x = (const float*)d_in[0];
    float* out = (float*)d_out;

    cudaFuncSetAttribute(rips_ecc_kernel,
                         cudaFuncAttributeMaxDynamicSharedMemorySize, SMEM_BYTES);

    ecc_zero_kernel<<<1, 64>>>();
    rips_ecc_kernel<<<NBLOCKS, NTHREADS, SMEM_BYTES>>>(x);
    ecc_cumsum_kernel<<<1, 32>>>(out);
}